// round 2
// baseline (speedup 1.0000x reference)
#include <cuda_runtime.h>
#include <math.h>

#define N_PTS 2048
#define DIMS 64
#define EPSV 0.1f
#define INV_EPS 10.0f
#define ITERS 100
#define THRESH 0.1f

// ---------------- device scratch (static, allocation-free) ----------------
__device__ __align__(16) float g_Ce[N_PTS * N_PTS];   // -C/eps, row-major [i][j]
__device__ __align__(16) float g_Ct[N_PTS * N_PTS];   // transpose of g_Ce [j][i]
__device__ __align__(16) float g_u[N_PTS];
__device__ __align__(16) float g_v[N_PTS];
__device__ __align__(16) float g_usc[N_PTS];          // u/eps
__device__ __align__(16) float g_vsc[N_PTS];          // v/eps
__device__ float g_du[N_PTS];
__device__ float g_dv[N_PTS];
__device__ float g_cost_part[N_PTS];
__device__ int   g_done;

// ---------------- init ----------------
__global__ void init_kernel() {
    int t = blockIdx.x * blockDim.x + threadIdx.x;
    if (t < N_PTS) {
        g_u[t] = 0.f; g_v[t] = 0.f; g_usc[t] = 0.f; g_vsc[t] = 0.f;
    }
    if (t == 0) g_done = 0;
}

// ---------------- cost matrix: Ce[i][j] = -||x_i - y_j||^2 / eps ----------------
// 64x64 output tile per block, 256 threads, 4x4 register microtile per thread.
__global__ void __launch_bounds__(256) compute_C(const float* __restrict__ x,
                                                 const float* __restrict__ y) {
    __shared__ float xt[64 * 68];  // [d][i], padded stride 68
    __shared__ float yt[64 * 68];  // [d][j]

    const int i0 = blockIdx.y * 64;
    const int j0 = blockIdx.x * 64;
    const int t  = threadIdx.x;

    // load tiles transposed (shared[d][row])
    for (int idx = t; idx < 64 * 64; idx += 256) {
        int r = idx >> 6, c = idx & 63;
        xt[c * 68 + r] = x[(i0 + r) * DIMS + c];
        yt[c * 68 + r] = y[(j0 + r) * DIMS + c];
    }
    __syncthreads();

    const int tx = t & 15;    // j microtile index
    const int ty = t >> 4;    // i microtile index

    float acc[4][4];
#pragma unroll
    for (int a = 0; a < 4; a++)
#pragma unroll
        for (int b = 0; b < 4; b++) acc[a][b] = 0.f;

#pragma unroll
    for (int d = 0; d < 64; d++) {
        float4 xv = *(const float4*)&xt[d * 68 + ty * 4];
        float4 yv = *(const float4*)&yt[d * 68 + tx * 4];
        float xs_[4] = {xv.x, xv.y, xv.z, xv.w};
        float ys_[4] = {yv.x, yv.y, yv.z, yv.w};
#pragma unroll
        for (int a = 0; a < 4; a++)
#pragma unroll
            for (int b = 0; b < 4; b++) {
                float dd = xs_[a] - ys_[b];
                acc[a][b] = fmaf(dd, dd, acc[a][b]);
            }
    }

    __syncthreads();                 // done with xt -> reuse as staging
    float* cts = xt;                 // [il * 65 + jl]

#pragma unroll
    for (int a = 0; a < 4; a++) {
        const int il = ty * 4 + a;
        const int i  = i0 + il;
        float4 ce4;
        ce4.x = -INV_EPS * acc[a][0];
        ce4.y = -INV_EPS * acc[a][1];
        ce4.z = -INV_EPS * acc[a][2];
        ce4.w = -INV_EPS * acc[a][3];
        *(float4*)&g_Ce[(size_t)i * N_PTS + j0 + tx * 4] = ce4;
        cts[il * 65 + tx * 4 + 0] = ce4.x;
        cts[il * 65 + tx * 4 + 1] = ce4.y;
        cts[il * 65 + tx * 4 + 2] = ce4.z;
        cts[il * 65 + tx * 4 + 3] = ce4.w;
    }
    __syncthreads();

    for (int idx = t; idx < 64 * 64; idx += 256) {
        int jl = idx >> 6, il = idx & 63;
        g_Ct[(size_t)(j0 + jl) * N_PTS + i0 + il] = cts[il * 65 + jl];
    }
}

// ---------------- one dual update (warp-per-row LSE) ----------------
// STEP==0: u update over rows of Ce with vsc; STEP==1: v update over rows of Ct with usc.
template <int STEP>
__global__ void __launch_bounds__(256) lse_step(float log_marg) {
    if (*(volatile int*)&g_done) return;

    const int gw   = (blockIdx.x * 256 + threadIdx.x) >> 5;  // row index
    const int lane = threadIdx.x & 31;

    const float4* C4 = (const float4*)(STEP == 0 ? g_Ce : g_Ct) + (size_t)gw * (N_PTS / 4);
    const float4* w4 = (const float4*)(STEP == 0 ? g_vsc : g_usc);

    float tv[64];
    float m = -3.4e38f;
#pragma unroll
    for (int k = 0; k < 16; k++) {
        float4 c = C4[lane + 32 * k];
        float4 w = w4[lane + 32 * k];
        float t0 = c.x + w.x, t1 = c.y + w.y, t2 = c.z + w.z, t3 = c.w + w.w;
        tv[4 * k + 0] = t0; tv[4 * k + 1] = t1; tv[4 * k + 2] = t2; tv[4 * k + 3] = t3;
        m = fmaxf(m, fmaxf(fmaxf(t0, t1), fmaxf(t2, t3)));
    }
#pragma unroll
    for (int o = 16; o; o >>= 1) m = fmaxf(m, __shfl_xor_sync(0xffffffffu, m, o));

    float s = 0.f;
#pragma unroll
    for (int e = 0; e < 64; e++) s += __expf(tv[e] - m);
#pragma unroll
    for (int o = 16; o; o >>= 1) s += __shfl_xor_sync(0xffffffffu, s, o);

    if (lane == 0) {
        float lse = m + __logf(s);
        float nd  = EPSV * (log_marg - lse);
        if (STEP == 0) {
            g_du[gw] = fabsf(nd - g_u[gw]);
            g_u[gw] = nd;
            g_usc[gw] = nd * INV_EPS;
        } else {
            g_dv[gw] = fabsf(nd - g_v[gw]);
            g_v[gw] = nd;
            g_vsc[gw] = nd * INV_EPS;
        }
    }
}

// ---------------- convergence check (deterministic tree reduce) ----------------
__global__ void check_kernel() {
    if (g_done) return;
    __shared__ float sm[1024];
    const int t = threadIdx.x;
    float s = g_du[t] + g_du[t + 1024] + g_dv[t] + g_dv[t + 1024];
    sm[t] = s;
    __syncthreads();
    for (int o = 512; o; o >>= 1) {
        if (t < o) sm[t] += sm[t + o];
        __syncthreads();
    }
    if (t == 0 && sm[0] < THRESH) g_done = 1;
}

// ---------------- final transport plan + cost partials ----------------
__global__ void __launch_bounds__(256) pi_cost_kernel(float* __restrict__ pi_out) {
    const int i = blockIdx.x;
    const int t = threadIdx.x;
    const float ui = g_usc[i];
    const float* crow = g_Ce + (size_t)i * N_PTS;
    float* prow = pi_out + (size_t)i * N_PTS;

    float s = 0.f;
#pragma unroll
    for (int k = 0; k < N_PTS / 256; k++) {
        int j = t + k * 256;
        float c = crow[j];
        float p = __expf(c + ui + g_vsc[j]);
        prow[j] = p;
        s = fmaf(p, c, s);  // accumulates pi * Ce  (Ce = -C/eps)
    }
    // deterministic block reduce
    const int lane = t & 31, w = t >> 5;
#pragma unroll
    for (int o = 16; o; o >>= 1) s += __shfl_xor_sync(0xffffffffu, s, o);
    __shared__ float sw[8];
    if (lane == 0) sw[w] = s;
    __syncthreads();
    if (t == 0) {
        float tot = 0.f;
#pragma unroll
        for (int k = 0; k < 8; k++) tot += sw[k];
        g_cost_part[i] = tot * (-EPSV);  // pi*C = pi * (-eps*Ce)
    }
}

__global__ void cost_reduce(float* __restrict__ cost_out) {
    __shared__ float sm[1024];
    const int t = threadIdx.x;
    sm[t] = g_cost_part[t] + g_cost_part[t + 1024];
    __syncthreads();
    for (int o = 512; o; o >>= 1) {
        if (t < o) sm[t] += sm[t + o];
        __syncthreads();
    }
    if (t == 0 && cost_out != nullptr) *cost_out = sm[0];
}

// ---------------- launch ----------------
extern "C" void kernel_launch(void* const* d_in, const int* in_sizes, int n_in,
                              void* d_out, int out_size) {
    const float* x = (const float*)d_in[0];
    const float* y = (const float*)d_in[1];
    float* out = (float*)d_out;

    const long long NM = (long long)N_PTS * N_PTS;
    float* cost_out = nullptr;
    float* pi_out   = out;
    if ((long long)out_size >= NM + 1) {       // (cost, pi) flattened, cost first
        cost_out = out;
        pi_out   = out + 1;
    }

    const float log_a = (float)log(1.0 / (double)N_PTS + 1e-8);  // N == M
    const float log_b = log_a;

    init_kernel<<<2, 1024>>>();
    dim3 cgrid(N_PTS / 64, N_PTS / 64);
    compute_C<<<cgrid, 256>>>(x, y);

    for (int it = 0; it < ITERS; it++) {
        lse_step<0><<<N_PTS * 32 / 256, 256>>>(log_a);  // u update (rows of Ce)
        lse_step<1><<<N_PTS * 32 / 256, 256>>>(log_b);  // v update (rows of Ct)
        check_kernel<<<1, 1024>>>();
    }

    pi_cost_kernel<<<N_PTS, 256>>>(pi_out);
    cost_reduce<<<1, 1024>>>(cost_out);
}

// round 3
// speedup vs baseline: 1.1128x; 1.1128x over previous
#include <cuda_runtime.h>
#include <math.h>

#define N_PTS 2048
#define DIMS 64
#define EPSV 0.1f
#define INV_EPS 10.0f
#define ITERS 100
#define THRESH 0.1f

#define SOLVE_BLOCKS 128          // == N_PTS / 16 warps; < SM count -> all co-resident
#define SOLVE_THREADS 512         // 16 warps per block, one row per warp

// ---------------- device scratch (static, allocation-free) ----------------
__device__ __align__(16) float g_Ce[N_PTS * N_PTS];   // -C/eps, row-major [i][j]
__device__ __align__(16) float g_Ct[N_PTS * N_PTS];   // transpose [j][i]
__device__ __align__(16) float g_usc[N_PTS];          // u/eps
__device__ __align__(16) float g_vsc[N_PTS];          // v/eps
__device__ float g_part[SOLVE_BLOCKS];                // per-block |du|+|dv| partials
__device__ float g_cost_part[N_PTS];
__device__ int          g_bar_count = 0;
__device__ volatile int g_bar_sense = 0;

// ---------------- software grid barrier (all blocks co-resident) ----------------
__device__ __forceinline__ void gsync(int& sense) {
    __threadfence();            // make this thread's global writes visible
    __syncthreads();
    if (threadIdx.x == 0) {
        sense ^= 1;
        int v = atomicAdd(&g_bar_count, 1);
        if (v == SOLVE_BLOCKS - 1) {
            g_bar_count = 0;
            __threadfence();
            g_bar_sense = sense;
        } else {
            while (g_bar_sense != sense) { __nanosleep(32); }
        }
        __threadfence();
    }
    __syncthreads();
}

// ---------------- cost matrix: Ce[i][j] = -||x_i - y_j||^2 / eps ----------------
__global__ void __launch_bounds__(256) compute_C(const float* __restrict__ x,
                                                 const float* __restrict__ y) {
    __shared__ float xt[64 * 68];  // [d][i], padded
    __shared__ float yt[64 * 68];  // [d][j]

    const int i0 = blockIdx.y * 64;
    const int j0 = blockIdx.x * 64;
    const int t  = threadIdx.x;

    for (int idx = t; idx < 64 * 64; idx += 256) {
        int r = idx >> 6, c = idx & 63;
        xt[c * 68 + r] = x[(i0 + r) * DIMS + c];
        yt[c * 68 + r] = y[(j0 + r) * DIMS + c];
    }
    __syncthreads();

    const int tx = t & 15;
    const int ty = t >> 4;

    float acc[4][4];
#pragma unroll
    for (int a = 0; a < 4; a++)
#pragma unroll
        for (int b = 0; b < 4; b++) acc[a][b] = 0.f;

#pragma unroll
    for (int d = 0; d < 64; d++) {
        float4 xv = *(const float4*)&xt[d * 68 + ty * 4];
        float4 yv = *(const float4*)&yt[d * 68 + tx * 4];
        float xs_[4] = {xv.x, xv.y, xv.z, xv.w};
        float ys_[4] = {yv.x, yv.y, yv.z, yv.w};
#pragma unroll
        for (int a = 0; a < 4; a++)
#pragma unroll
            for (int b = 0; b < 4; b++) {
                float dd = xs_[a] - ys_[b];
                acc[a][b] = fmaf(dd, dd, acc[a][b]);
            }
    }

    __syncthreads();
    float* cts = xt;

#pragma unroll
    for (int a = 0; a < 4; a++) {
        const int il = ty * 4 + a;
        const int i  = i0 + il;
        float4 ce4;
        ce4.x = -INV_EPS * acc[a][0];
        ce4.y = -INV_EPS * acc[a][1];
        ce4.z = -INV_EPS * acc[a][2];
        ce4.w = -INV_EPS * acc[a][3];
        *(float4*)&g_Ce[(size_t)i * N_PTS + j0 + tx * 4] = ce4;
        cts[il * 65 + tx * 4 + 0] = ce4.x;
        cts[il * 65 + tx * 4 + 1] = ce4.y;
        cts[il * 65 + tx * 4 + 2] = ce4.z;
        cts[il * 65 + tx * 4 + 3] = ce4.w;
    }
    __syncthreads();

    for (int idx = t; idx < 64 * 64; idx += 256) {
        int jl = idx >> 6, il = idx & 63;
        g_Ct[(size_t)(j0 + jl) * N_PTS + i0 + il] = cts[il * 65 + jl];
    }
}

// ---------------- warp-collective online LSE over one 2048-wide row ----------------
// returns row logsumexp on lane 0 (valid on all lanes after shuffle reduce)
__device__ __forceinline__ float row_lse(const float4* __restrict__ C4,
                                         const float4* __restrict__ w4,
                                         int lane) {
    float m = -3.4e38f, s = 0.f;
#pragma unroll
    for (int k = 0; k < 16; k++) {
        float4 c = C4[lane + 32 * k];
        float4 w = w4[lane + 32 * k];
        float t0 = c.x + w.x, t1 = c.y + w.y, t2 = c.z + w.z, t3 = c.w + w.w;
        float mx = fmaxf(fmaxf(t0, t1), fmaxf(t2, t3));
        if (mx > m) { s *= __expf(m - mx); m = mx; }
        s += __expf(t0 - m) + __expf(t1 - m) + __expf(t2 - m) + __expf(t3 - m);
    }
#pragma unroll
    for (int o = 16; o; o >>= 1) {
        float mo = __shfl_xor_sync(0xffffffffu, m, o);
        float so = __shfl_xor_sync(0xffffffffu, s, o);
        float mn = fmaxf(m, mo);
        s = s * __expf(m - mn) + so * __expf(mo - mn);
        m = mn;
    }
    return m + __logf(s);
}

// ---------------- persistent Sinkhorn solver (all iterations, one launch) ----------------
__global__ void __launch_bounds__(SOLVE_THREADS, 1) solve_kernel(float log_marg) {
    const int tid  = threadIdx.x;
    const int w    = tid >> 5;
    const int lane = tid & 31;
    const int row  = blockIdx.x * 16 + w;      // one warp per row, exact cover

    __shared__ float sdu[16];
    __shared__ float sdv[16];
    __shared__ float sflag;

    int sense = g_bar_sense;                    // persistent across graph replays

    // init duals
    if (tid < 16) {
        g_usc[blockIdx.x * 16 + tid] = 0.f;
        g_vsc[blockIdx.x * 16 + tid] = 0.f;
    }
    float u_reg = 0.f, v_reg = 0.f;             // lane 0 holds the live value

    gsync(sense);

    const float4* Crow = (const float4*)g_Ce + (size_t)row * (N_PTS / 4);
    const float4* Trow = (const float4*)g_Ct + (size_t)row * (N_PTS / 4);
    const float4* usc4 = (const float4*)g_usc;
    const float4* vsc4 = (const float4*)g_vsc;

    for (int it = 0; it < ITERS; it++) {
        // ---- u update: u_i = eps*(log_a - LSE_j(Ce_ij + vsc_j)) ----
        {
            float lse = row_lse(Crow, vsc4, lane);
            if (lane == 0) {
                float nd = EPSV * (log_marg - lse);
                sdu[w] = fabsf(nd - u_reg);
                u_reg = nd;
                g_usc[row] = nd * INV_EPS;
            }
        }
        gsync(sense);

        // ---- v update: v_j = eps*(log_b - LSE_i(Ct_ji + usc_i)) ----
        {
            float lse = row_lse(Trow, usc4, lane);
            if (lane == 0) {
                float nd = EPSV * (log_marg - lse);
                sdv[w] = fabsf(nd - v_reg);
                v_reg = nd;
                g_vsc[row] = nd * INV_EPS;
            }
        }
        __syncthreads();
        if (tid == 0) {
            float p = 0.f;
#pragma unroll
            for (int k = 0; k < 16; k++) p += sdu[k] + sdv[k];
            g_part[blockIdx.x] = p;
        }
        gsync(sense);

        // ---- convergence decision (redundantly computed by every block) ----
        if (tid == 0) {
            float tot = 0.f;
            for (int k = 0; k < SOLVE_BLOCKS; k++) tot += g_part[k];
            sflag = tot;
        }
        __syncthreads();
        if (sflag < THRESH) break;              // all blocks break together
    }
}

// ---------------- final transport plan + cost ----------------
__global__ void __launch_bounds__(256) pi_cost_kernel(float* __restrict__ pi_out) {
    const int i = blockIdx.x;
    const int t = threadIdx.x;
    const float ui = g_usc[i];
    const float* crow = g_Ce + (size_t)i * N_PTS;
    float* prow = pi_out + (size_t)i * N_PTS;

    float s = 0.f;
#pragma unroll
    for (int k = 0; k < N_PTS / 256; k++) {
        int j = t + k * 256;
        float c = crow[j];
        float p = __expf(c + ui + g_vsc[j]);
        prow[j] = p;
        s = fmaf(p, c, s);
    }
    const int lane = t & 31, w = t >> 5;
#pragma unroll
    for (int o = 16; o; o >>= 1) s += __shfl_xor_sync(0xffffffffu, s, o);
    __shared__ float sw[8];
    if (lane == 0) sw[w] = s;
    __syncthreads();
    if (t == 0) {
        float tot = 0.f;
#pragma unroll
        for (int k = 0; k < 8; k++) tot += sw[k];
        g_cost_part[i] = tot * (-EPSV);
    }
}

__global__ void cost_reduce(float* __restrict__ cost_out) {
    __shared__ float sm[1024];
    const int t = threadIdx.x;
    sm[t] = g_cost_part[t] + g_cost_part[t + 1024];
    __syncthreads();
    for (int o = 512; o; o >>= 1) {
        if (t < o) sm[t] += sm[t + o];
        __syncthreads();
    }
    if (t == 0 && cost_out != nullptr) *cost_out = sm[0];
}

// ---------------- launch ----------------
extern "C" void kernel_launch(void* const* d_in, const int* in_sizes, int n_in,
                              void* d_out, int out_size) {
    const float* x = (const float*)d_in[0];
    const float* y = (const float*)d_in[1];
    float* out = (float*)d_out;

    const long long NM = (long long)N_PTS * N_PTS;
    float* cost_out = nullptr;
    float* pi_out   = out;
    if ((long long)out_size >= NM + 1) {
        cost_out = out;
        pi_out   = out + 1;
    }

    const float log_a = (float)log(1.0 / (double)N_PTS + 1e-8);

    dim3 cgrid(N_PTS / 64, N_PTS / 64);
    compute_C<<<cgrid, 256>>>(x, y);
    solve_kernel<<<SOLVE_BLOCKS, SOLVE_THREADS>>>(log_a);
    pi_cost_kernel<<<N_PTS, 256>>>(pi_out);
    cost_reduce<<<1, 1024>>>(cost_out);
}